// round 7
// baseline (speedup 1.0000x reference)
#include <cuda_runtime.h>
#include <cstdint>
#include <math.h>

// Problem constants
#define BB 64
#define SS 1024
#define II 512
#define HH 512
#define NPANEL 128   // persistent CTAs: 64 panels per layer, 1 CTA/SM
#define JPC 8        // hidden units per CTA
#define TPB 256      // 8 warps -> 2 per SMSP (latency hiding)
#define KT 64        // k-chunk staged in SMEM
#define NCH 8        // chunks per k-half (each half covers 512 k)
#define AP 68        // A smem row pitch: 68 floats = 17 x 16B -> conflict-free STS.128/LDS

#define WS_FLOATS (1024*32)          // duplicated weight panel: [k][32]
#define AS_FLOATS (KT*AP)            // 4352 floats per A buffer
#define SMEM_BYTES ((WS_FLOATS + 4*AS_FLOATS)*4)   // 200704 B (< 227KB, 1 CTA/SM)

typedef unsigned long long ull;

// Scratch (device globals: allocation-free per harness rules)
__device__ float g_Wpanel[NPANEL*1024*16];  // [panel][k][16] cols interleaved (gate j, cand j)
__device__ float g_h0[2][BB*HH];            // ping-pong hidden, layer 0
__device__ float g_h1[2][BB*HH];            // ping-pong hidden, layer 1
__device__ unsigned g_arrive;               // grid-barrier monotonic arrival counter

__device__ __forceinline__ ull ffma2(ull a, ull b, ull c){
    ull d;
    asm("fma.rn.f32x2 %0, %1, %2, %3;" : "=l"(d) : "l"(a), "l"(b), "l"(c));
    return d;
}
__device__ __forceinline__ void unpack2(ull v, float& lo, float& hi){
    asm("mov.b64 {%0, %1}, %2;" : "=f"(lo), "=f"(hi) : "l"(v));
}

// Build combined, column-interleaved weight panels:
// panel p: layer l = p>>6, hidden units j0..j0+7 with j0 = (p&63)*8.
// g_Wpanel[p][k][2*jj+0] = gate weight Wg[l][k][j]   (Wg rows already [inp;h] ordered)
// g_Wpanel[p][k][2*jj+1] = cand weight (k<512 ? Wi[l][k][j] : Wh[l][k-512][j])
__global__ void prep_kernel(const float* __restrict__ Wg,
                            const float* __restrict__ Wi,
                            const float* __restrict__ Wh){
    int idx = blockIdx.x * blockDim.x + threadIdx.x;
    if (idx >= NPANEL*1024*16) return;
    int cc = idx & 15;
    int k  = (idx >> 4) & 1023;
    int p  = idx >> 14;
    int l  = p >> 6;
    int j  = (p & 63)*JPC + (cc >> 1);
    float v;
    if ((cc & 1) == 0) {
        v = Wg[(size_t)(l*1024 + k)*512 + j];
    } else {
        v = (k < II) ? Wi[(size_t)(l*512 + k)*512 + j]
                     : Wh[(size_t)(l*512 + (k - II))*512 + j];
    }
    g_Wpanel[idx] = v;
}

// Zero hidden state + barrier counter (runs at the start of every replay).
__global__ void init_kernel(){
    int i = blockIdx.x * blockDim.x + threadIdx.x;
    if (i == 0) g_arrive = 0u;
    if (i < BB*HH){
        g_h0[0][i] = 0.f; g_h0[1][i] = 0.f;
        g_h1[0][i] = 0.f; g_h1[1][i] = 0.f;
    }
}

// Persistent kernel: 128 CTAs (one per SM), 256 threads each, looping over
// phases s=0..SS with a device grid barrier between phases.
//   phase s:  CTAs l==0 compute h0[s]   = gru(x[:,s,:], h0[s-1])   (s < SS)
//             CTAs l==1 compute h1[s-1] = gru(h0[s-1],  h1[s-2])   (s >= 1)
// Within a CTA, warps 0-3 ("half 0") handle k in [0,512) (the input matrix),
// warps 4-7 ("half 1") handle k in [512,1024) (the hidden matrix); partial
// sums are combined through SMEM before the GRU epilogue.
__global__ void __launch_bounds__(TPB, 1)
persist_kernel(const float* __restrict__ x, const float* __restrict__ bg,
               const float* __restrict__ bi, float* __restrict__ out,
               int out_size)
{
    const int p = blockIdx.x;
    const int l = p >> 6;
    const int t = threadIdx.x;
    const int half = t >> 7;     // 0: k in [0,512), 1: k in [512,1024)
    const int ht   = t & 127;    // thread within half

    extern __shared__ float smf[];
    float* ws = smf;                              // [1024][32] duplicated weights (persistent)
    float* ab[4];                                 // A tile double buffers, 2 per half
    ab[0] = smf + WS_FLOATS;
    ab[1] = ab[0] + AS_FLOATS;
    ab[2] = ab[1] + AS_FLOATS;
    ab[3] = ab[2] + AS_FLOATS;
    float* myb0 = ab[2*half];
    float* myb1 = ab[2*half + 1];
    float* px   = ab[2];                          // partial-sum exchange area (free post-compute)

    // ---- load weight panel into SMEM ONCE, duplicating scalars into pairs for FFMA2 ----
    {
        const float4* gw = ((const float4*)g_Wpanel) + (size_t)p * 4096;
        float4* ws4 = (float4*)ws;
        #pragma unroll
        for (int it = 0; it < 16; ++it){
            int i = t + it*TPB;                 // 0..4095 float4s
            float4 v = gw[i];
            int k = i >> 2, q = i & 3;
            ws4[k*8 + q*2 + 0] = make_float4(v.x, v.x, v.y, v.y);
            ws4[k*8 + q*2 + 1] = make_float4(v.z, v.z, v.w, v.w);
        }
    }
    __syncthreads();

    const int jj = ht >> 4;          // 0..7 hidden unit within panel
    const int m0 = (ht & 15) * 4;    // 4 batch rows
    const int klocal = ht & 63;
    const int mb     = (ht >> 6) & 1;  // m-half for staging (m 0..31 / 32..63)
    const int j = (p & 63)*JPC + jj;
    const float bgv = bg[l*HH + j];
    const float biv = bi[l*HH + j];
    const float* wbase = ws + jj*4;

    unsigned bar_target = 0;

    #pragma unroll 1
    for (int s = 0; s <= SS; ++s){
        const bool active = !((l == 0 && s == SS) || (l == 1 && s == 0));
        if (active){
            int pb = s & 1;
            const float* h0prev  = g_h0[pb ^ 1];
            float*       h0out   = g_h0[pb];
            const float* h1prev2 = g_h1[pb];
            float*       h1out   = g_h1[pb ^ 1];

            // half 0 streams the "input" matrix, half 1 the "hidden" matrix
            const float* src; size_t stride;
            const float* hupd; float* hout;
            if (l == 0){
                if (half == 0){ src = x + (size_t)s * II; stride = (size_t)SS * II; }
                else          { src = h0prev;             stride = HH; }
                hupd = h0prev;  hout = h0out;
            } else {
                if (half == 0){ src = h0prev;  stride = HH; }
                else          { src = h1prev2; stride = HH; }
                hupd = h1prev2; hout = h1out;
            }

            // ---- A staging: [k][m] tiles (pitch AP), contiguous STS.128 ----
            float pf[32];
            auto prefetch = [&](int c){
                int kcol = c*KT + klocal;
                #pragma unroll
                for (int i = 0; i < 32; ++i){
                    int m = 32*mb + i;
                    pf[i] = src[(size_t)m*stride + kcol];
                }
            };
            auto sts = [&](float* buf){
                float* dst = buf + klocal*AP + 32*mb;
                #pragma unroll
                for (int q = 0; q < 8; ++q)
                    *(float4*)(dst + 4*q) = make_float4(pf[4*q], pf[4*q+1], pf[4*q+2], pf[4*q+3]);
            };

            ull ag0 = 0, ag1 = 0, ac0 = 0, ac1 = 0;
            auto compute = [&](const float* buf, int gc){
                const float* wc = wbase + gc*KT*32;
                #pragma unroll
                for (int kk = 0; kk < KT; ++kk){
                    const float* ar = buf + kk*AP + m0;
                    ull a01 = *(const ull*)(ar);
                    ull a23 = *(const ull*)(ar + 2);
                    // weights: gate-pair + cand-pair are 16B contiguous, 16B aligned
                    ulonglong2 w2 = *(const ulonglong2*)(wc + kk*32);
                    ag0 = ffma2(a01, w2.x, ag0);
                    ag1 = ffma2(a23, w2.x, ag1);
                    ac0 = ffma2(a01, w2.y, ac0);
                    ac1 = ffma2(a23, w2.y, ac1);
                }
            };

            prefetch(0);
            sts(myb0);
            __syncthreads();
            prefetch(1);
            #pragma unroll 1
            for (int c = 0; c < NCH; ++c){
                float* cur = (c & 1) ? myb1 : myb0;
                float* nxt = (c & 1) ? myb0 : myb1;
                compute(cur, half*NCH + c);
                if (c + 1 < NCH) sts(nxt);
                __syncthreads();
                if (c + 2 < NCH) prefetch(c + 2);
            }

            // ---- combine k-halves through SMEM ----
            float gv[4], cv[4];
            unpack2(ag0, gv[0], gv[1]); unpack2(ag1, gv[2], gv[3]);
            unpack2(ac0, cv[0], cv[1]); unpack2(ac1, cv[2], cv[3]);
            if (half == 1){
                float* d = px + ht*8;
                *(float4*)(d)     = make_float4(gv[0], gv[1], gv[2], gv[3]);
                *(float4*)(d + 4) = make_float4(cv[0], cv[1], cv[2], cv[3]);
            }
            __syncthreads();

            if (half == 0){
                const float* d = px + ht*8;
                float4 pg = *(const float4*)(d);
                float4 pc = *(const float4*)(d + 4);
                gv[0] += pg.x; gv[1] += pg.y; gv[2] += pg.z; gv[3] += pg.w;
                cv[0] += pc.x; cv[1] += pc.y; cv[2] += pc.z; cv[3] += pc.w;

                // ---- epilogue: GRU update ----
                #pragma unroll
                for (int r = 0; r < 4; ++r){
                    int m = m0 + r;
                    float zin = gv[r] + bgv;
                    float z   = __fdividef(1.f, 1.f + __expf(-zin));
                    float cin = cv[r] + biv;
                    float av  = fabsf(cin);
                    float e   = __expf(-2.f*av);
                    float cd  = copysignf(__fdividef(1.f - e, 1.f + e), cin);
                    float hp  = hupd[(size_t)m*HH + j];
                    float hn  = hp + z*(cd - hp);
                    hout[(size_t)m*HH + j] = hn;
                    if (l == 1)
                        out[(size_t)m*SS*HH + (size_t)(s-1)*HH + j] = hn;
                }
            }
        }

        // ---- grid barrier (monotonic counter; reset by init_kernel each replay) ----
        bar_target += NPANEL;
        __syncthreads();
        if (t == 0){
            __threadfence();
            atomicAdd(&g_arrive, 1u);
            unsigned v;
            do {
                asm volatile("ld.acquire.gpu.global.u32 %0, [%1];"
                             : "=r"(v) : "l"(&g_arrive) : "memory");
            } while (v < bar_target);
        }
        __syncthreads();
    }

    // ---- tail: final hidden states appended after output ----
    // h0[S-1] ended in g_h0[1] (written at phase S-1, pb=1);
    // h1[S-1] ended in g_h1[1] (written at phase S,   pb^1=1).
    long long base = (long long)BB*SS*HH;
    if (base + 2LL*BB*HH <= (long long)out_size){
        for (int i = p*TPB + t; i < BB*HH; i += NPANEL*TPB){
            out[base + i]         = g_h0[1][i];
            out[base + BB*HH + i] = g_h1[1][i];
        }
    }
}

extern "C" void kernel_launch(void* const* d_in, const int* in_sizes, int n_in,
                              void* d_out, int out_size)
{
    const float* x  = (const float*)d_in[0];
    const float* Wg = (const float*)d_in[1];
    const float* bg = (const float*)d_in[2];
    const float* Wi = (const float*)d_in[3];
    const float* bi = (const float*)d_in[4];
    const float* Wh = (const float*)d_in[5];
    float* out = (float*)d_out;

    cudaFuncSetAttribute(persist_kernel, cudaFuncAttributeMaxDynamicSharedMemorySize, SMEM_BYTES);

    prep_kernel<<<(NPANEL*1024*16 + 255)/256, 256>>>(Wg, Wi, Wh);
    init_kernel<<<(BB*HH + 255)/256, 256>>>();
    persist_kernel<<<NPANEL, TPB, SMEM_BYTES>>>(x, bg, bi, out, out_size);
}

// round 9
// speedup vs baseline: 1.4548x; 1.4548x over previous
#include <cuda_runtime.h>
#include <cstdint>
#include <math.h>

// Problem constants
#define BB 64
#define SS 1024
#define II 512
#define HH 512
#define NPANEL 128   // persistent CTAs: 64 panels per layer, 1 CTA/SM
#define JPC 8        // hidden units per CTA
#define TPB 256      // warps 0-3: compute crew, warps 4-7: staging crew
#define KT 64        // k-chunk staged in SMEM
#define NCHUNK 16    // 1024 / 64
#define AP 66        // A smem row pitch (even -> 8B LDS, 2-way STS conflicts only)

#define WS_FLOATS (1024*32)          // duplicated weight panel: [k][32]
#define AS_FLOATS (KT*AP)            // 4224 floats per A buffer
#define SMEM_BYTES ((WS_FLOATS + 3*AS_FLOATS)*4)   // 181760 B (< 227KB, 1 CTA/SM)

typedef unsigned long long ull;

// Scratch (device globals: allocation-free per harness rules)
__device__ float g_Wpanel[NPANEL*1024*16];  // [panel][k][16] cols interleaved (gate j, cand j)
__device__ float g_h0[2][BB*HH];            // ping-pong hidden, layer 0
__device__ float g_h1[2][BB*HH];            // ping-pong hidden, layer 1
__device__ unsigned g_arrive;               // grid-barrier monotonic arrival counter

__device__ __forceinline__ ull ffma2(ull a, ull b, ull c){
    ull d;
    asm("fma.rn.f32x2 %0, %1, %2, %3;" : "=l"(d) : "l"(a), "l"(b), "l"(c));
    return d;
}
__device__ __forceinline__ void unpack2(ull v, float& lo, float& hi){
    asm("mov.b64 {%0, %1}, %2;" : "=f"(lo), "=f"(hi) : "l"(v));
}

// Build combined, column-interleaved weight panels:
// panel p: layer l = p>>6, hidden units j0..j0+7 with j0 = (p&63)*8.
// g_Wpanel[p][k][2*jj+0] = gate weight Wg[l][k][j]   (Wg rows already [inp;h] ordered)
// g_Wpanel[p][k][2*jj+1] = cand weight (k<512 ? Wi[l][k][j] : Wh[l][k-512][j])
__global__ void prep_kernel(const float* __restrict__ Wg,
                            const float* __restrict__ Wi,
                            const float* __restrict__ Wh){
    int idx = blockIdx.x * blockDim.x + threadIdx.x;
    if (idx >= NPANEL*1024*16) return;
    int cc = idx & 15;
    int k  = (idx >> 4) & 1023;
    int p  = idx >> 14;
    int l  = p >> 6;
    int j  = (p & 63)*JPC + (cc >> 1);
    float v;
    if ((cc & 1) == 0) {
        v = Wg[(size_t)(l*1024 + k)*512 + j];
    } else {
        v = (k < II) ? Wi[(size_t)(l*512 + k)*512 + j]
                     : Wh[(size_t)(l*512 + (k - II))*512 + j];
    }
    g_Wpanel[idx] = v;
}

// Zero hidden state + barrier counter (runs at the start of every replay).
__global__ void init_kernel(){
    int i = blockIdx.x * blockDim.x + threadIdx.x;
    if (i == 0) g_arrive = 0u;
    if (i < BB*HH){
        g_h0[0][i] = 0.f; g_h0[1][i] = 0.f;
        g_h1[0][i] = 0.f; g_h1[1][i] = 0.f;
    }
}

// Persistent kernel: 128 CTAs (one per SM), 256 threads, looping over phases
// s=0..SS with a device grid barrier between phases.
//   phase s:  CTAs l==0 compute h0[s]   = gru(x[:,s,:], h0[s-1])   (s < SS)
//             CTAs l==1 compute h1[s-1] = gru(h0[s-1],  h1[s-2])   (s >= 1)
// Crew split: threads 0-127 (warps 0-3) are the COMPUTE crew — pure
// LDS+FFMA2 inner loop, no global loads. Threads 128-255 (warps 4-7) are the
// STAGING crew — LDG prefetch + STS into a triple-buffered A tile, one chunk
// ahead of compute. One warp of each crew per SMSP: the staging warp absorbs
// memory latency and fills issue slots while the compute warp owns the FMA pipe.
__global__ void __launch_bounds__(TPB, 1)
persist_kernel(const float* __restrict__ x, const float* __restrict__ bg,
               const float* __restrict__ bi, float* __restrict__ out,
               int out_size)
{
    const int p = blockIdx.x;
    const int l = p >> 6;
    const int t = threadIdx.x;
    const int crew = t >> 7;     // 0 = compute, 1 = staging
    const int ht   = t & 127;

    extern __shared__ float smf[];
    float* ws = smf;                              // [1024][32] duplicated weights
    float* ab[3];                                 // A tile triple buffer
    ab[0] = smf + WS_FLOATS;
    ab[1] = ab[0] + AS_FLOATS;
    ab[2] = ab[1] + AS_FLOATS;

    // ---- load weight panel into SMEM ONCE, duplicating scalars into FFMA2 pairs ----
    {
        const float4* gw = ((const float4*)g_Wpanel) + (size_t)p * 4096;
        float4* ws4 = (float4*)ws;
        #pragma unroll
        for (int it = 0; it < 16; ++it){
            int i = t + it*TPB;                 // 0..4095 float4s
            float4 v = gw[i];
            int k = i >> 2, q = i & 3;
            ws4[k*8 + q*2 + 0] = make_float4(v.x, v.x, v.y, v.y);
            ws4[k*8 + q*2 + 1] = make_float4(v.z, v.z, v.w, v.w);
        }
    }
    __syncthreads();

    // compute-crew mapping
    const int jj = ht >> 4;          // 0..7 hidden unit within panel
    const int m0 = (ht & 15) * 4;    // 4 batch rows
    // staging-crew mapping
    const int klocal = ht & 63;
    const int mb     = ht >> 6;      // 0 or 1
    const int j = (p & 63)*JPC + jj;
    const float bgv = bg[l*HH + j];
    const float biv = bi[l*HH + j];
    const float* wbase = ws + jj*4;

    unsigned bar_target = 0;

    #pragma unroll 1
    for (int s = 0; s <= SS; ++s){
        const bool active = !((l == 0 && s == SS) || (l == 1 && s == 0));
        if (active){
            int pb = s & 1;
            const float* h0prev  = g_h0[pb ^ 1];
            float*       h0out   = g_h0[pb];
            const float* h1prev2 = g_h1[pb];
            float*       h1out   = g_h1[pb ^ 1];

            const float* baseLo; size_t strideLo;
            const float* baseHi;
            const float* hupd; float* hout;
            if (l == 0){
                baseLo = x + (size_t)s * II;  strideLo = (size_t)SS * II;
                baseHi = h0prev;  hupd = h0prev;  hout = h0out;
            } else {
                baseLo = h0prev;  strideLo = HH;
                baseHi = h1prev2; hupd = h1prev2; hout = h1out;
            }

            float pf[32];
            auto prefetch = [&](int c){
                int k = c*KT + klocal;
                #pragma unroll
                for (int i = 0; i < 32; ++i){
                    int m = 2*i + mb;
                    pf[i] = (k < II) ? baseLo[(size_t)m*strideLo + k]
                                     : baseHi[(size_t)m*HH + (k - II)];
                }
            };
            auto sts = [&](float* buf){
                #pragma unroll
                for (int i = 0; i < 32; ++i)
                    buf[klocal*AP + 2*i + mb] = pf[i];
            };

            ull ag0 = 0, ag1 = 0, ac0 = 0, ac1 = 0;
            auto compute = [&](const float* buf, int c){
                const float* wc = wbase + c*KT*32;
                #pragma unroll
                for (int kk = 0; kk < KT; ++kk){
                    const float* ar = buf + kk*AP + m0;
                    ull a01 = *(const ull*)(ar);
                    ull a23 = *(const ull*)(ar + 2);
                    ulonglong2 w2 = *(const ulonglong2*)(wc + kk*32);
                    ag0 = ffma2(a01, w2.x, ag0);
                    ag1 = ffma2(a23, w2.x, ag1);
                    ac0 = ffma2(a01, w2.y, ac0);
                    ac1 = ffma2(a23, w2.y, ac1);
                }
            };

            // Prologue: staging crew fills buffer 0 and prefetches chunk 1.
            if (crew == 1){
                prefetch(0);
                sts(ab[0]);
                prefetch(1);
            }
            __syncthreads();

            // Pipeline: at iter c, compute reads ab[c%3] while staging writes
            // ab[(c+1)%3] (from regs prefetched last iter) and prefetches c+2.
            // Buffer (c+1)%3 was last read at iter c-2, so no WAR hazard.
            #pragma unroll 1
            for (int c = 0; c < NCHUNK; ++c){
                if (crew == 0){
                    compute(ab[c % 3], c);
                } else {
                    if (c + 1 < NCHUNK){
                        sts(ab[(c + 1) % 3]);
                        if (c + 2 < NCHUNK) prefetch(c + 2);
                    }
                }
                __syncthreads();
            }

            // ---- epilogue: GRU update (compute crew only) ----
            if (crew == 0){
                float gv[4], cv[4];
                unpack2(ag0, gv[0], gv[1]); unpack2(ag1, gv[2], gv[3]);
                unpack2(ac0, cv[0], cv[1]); unpack2(ac1, cv[2], cv[3]);
                #pragma unroll
                for (int r = 0; r < 4; ++r){
                    int m = m0 + r;
                    float zin = gv[r] + bgv;
                    float z   = __fdividef(1.f, 1.f + __expf(-zin));
                    float cin = cv[r] + biv;
                    float av  = fabsf(cin);
                    float e   = __expf(-2.f*av);
                    float cd  = copysignf(__fdividef(1.f - e, 1.f + e), cin);
                    float hp  = hupd[(size_t)m*HH + j];
                    float hn  = hp + z*(cd - hp);
                    hout[(size_t)m*HH + j] = hn;
                    if (l == 1)
                        out[(size_t)m*SS*HH + (size_t)(s-1)*HH + j] = hn;
                }
            }
        }

        // ---- grid barrier (monotonic counter; reset by init_kernel each replay) ----
        bar_target += NPANEL;
        __syncthreads();
        if (t == 0){
            __threadfence();
            atomicAdd(&g_arrive, 1u);
            unsigned v;
            do {
                asm volatile("ld.acquire.gpu.global.u32 %0, [%1];"
                             : "=r"(v) : "l"(&g_arrive) : "memory");
            } while (v < bar_target);
        }
        __syncthreads();
    }

    // ---- tail: final hidden states appended after output ----
    // h0[S-1] ended in g_h0[1] (written at phase S-1, pb=1);
    // h1[S-1] ended in g_h1[1] (written at phase S,   pb^1=1).
    long long base = (long long)BB*SS*HH;
    if (base + 2LL*BB*HH <= (long long)out_size){
        for (int i = p*TPB + t; i < BB*HH; i += NPANEL*TPB){
            out[base + i]         = g_h0[1][i];
            out[base + BB*HH + i] = g_h1[1][i];
        }
    }
}

extern "C" void kernel_launch(void* const* d_in, const int* in_sizes, int n_in,
                              void* d_out, int out_size)
{
    const float* x  = (const float*)d_in[0];
    const float* Wg = (const float*)d_in[1];
    const float* bg = (const float*)d_in[2];
    const float* Wi = (const float*)d_in[3];
    const float* bi = (const float*)d_in[4];
    const float* Wh = (const float*)d_in[5];
    float* out = (float*)d_out;

    cudaFuncSetAttribute(persist_kernel, cudaFuncAttributeMaxDynamicSharedMemorySize, SMEM_BYTES);

    prep_kernel<<<(NPANEL*1024*16 + 255)/256, 256>>>(Wg, Wi, Wh);
    init_kernel<<<(BB*HH + 255)/256, 256>>>();
    persist_kernel<<<NPANEL, TPB, SMEM_BYTES>>>(x, bg, bi, out, out_size);
}

// round 10
// speedup vs baseline: 2.6833x; 1.8444x over previous
#include <cuda_runtime.h>
#include <cstdint>
#include <math.h>

// Problem constants
#define BB 64
#define SS 1024
#define II 512
#define HH 512
#define NPANEL 128   // persistent CTAs: 64 panels per layer, 1 CTA/SM
#define JPC 8        // hidden units per CTA
#define TPB 128      // 4 warps; warp w owns k in [256w, 256w+256)
#define KT 16        // k-chunk staged per warp
#define NCHUNK 16    // 256 / 16

#define WS_FLOATS (1024*16)      // natural weight panel [k][16]: (g0,c0,g1,c1,...)
#define ABUF_FLOATS (KT*64)      // 1024 floats per buffer
#define PX_ULL (4*8*64)          // 2048 ull = 16KB partial-sum exchange
#define SMEM_BYTES ((WS_FLOATS + 8*ABUF_FLOATS)*4 + PX_ULL*8)  // 114688 B

typedef unsigned long long ull;

// Scratch (device globals: allocation-free per harness rules)
__device__ float g_Wpanel[NPANEL*1024*16];  // [panel][k][16] cols interleaved (gate j, cand j)
__device__ float g_h0[2][BB*HH];            // ping-pong hidden, layer 0
__device__ float g_h1[2][BB*HH];            // ping-pong hidden, layer 1
__device__ unsigned g_arrive;               // grid-barrier monotonic arrival counter

__device__ __forceinline__ ull ffma2(ull a, ull b, ull c){
    ull d;
    asm("fma.rn.f32x2 %0, %1, %2, %3;" : "=l"(d) : "l"(a), "l"(b), "l"(c));
    return d;
}
__device__ __forceinline__ ull packdup(float a){
    ull r;
    asm("mov.b64 %0, {%1, %1};" : "=l"(r) : "f"(a));
    return r;
}
__device__ __forceinline__ void unpack2(ull v, float& lo, float& hi){
    asm("mov.b64 {%0, %1}, %2;" : "=f"(lo), "=f"(hi) : "l"(v));
}

// Build combined, column-interleaved weight panels (natural, no duplication):
// panel p: layer l = p>>6, hidden units j0..j0+7 with j0 = (p&63)*8.
// g_Wpanel[p][k][2*jj+0] = gate weight Wg[l][k][j]   (Wg rows already [inp;h] ordered)
// g_Wpanel[p][k][2*jj+1] = cand weight (k<512 ? Wi[l][k][j] : Wh[l][k-512][j])
__global__ void prep_kernel(const float* __restrict__ Wg,
                            const float* __restrict__ Wi,
                            const float* __restrict__ Wh){
    int idx = blockIdx.x * blockDim.x + threadIdx.x;
    if (idx >= NPANEL*1024*16) return;
    int cc = idx & 15;
    int k  = (idx >> 4) & 1023;
    int p  = idx >> 14;
    int l  = p >> 6;
    int j  = (p & 63)*JPC + (cc >> 1);
    float v;
    if ((cc & 1) == 0) {
        v = Wg[(size_t)(l*1024 + k)*512 + j];
    } else {
        v = (k < II) ? Wi[(size_t)(l*512 + k)*512 + j]
                     : Wh[(size_t)(l*512 + (k - II))*512 + j];
    }
    g_Wpanel[idx] = v;
}

// Zero hidden state + barrier counter (runs at the start of every replay).
__global__ void init_kernel(){
    int i = blockIdx.x * blockDim.x + threadIdx.x;
    if (i == 0) g_arrive = 0u;
    if (i < BB*HH){
        g_h0[0][i] = 0.f; g_h0[1][i] = 0.f;
        g_h1[0][i] = 0.f; g_h1[1][i] = 0.f;
    }
}

// Persistent kernel: 128 CTAs (one per SM), 128 threads, phases s=0..SS with a
// device grid barrier between phases.
//   phase s:  CTAs l==0 compute h0[s]   = gru(x[:,s,:], h0[s-1])   (s < SS)
//             CTAs l==1 compute h1[s-1] = gru(h0[s-1],  h1[s-2])   (s >= 1)
// k-split: warp w owns k in [256w, 256w+256); each warp computes the full
// 8j x 64m x (gate,cand) tile for its k range with 16 f32x2 accumulators,
// stages its own A chunks (16k x 64m, XOR-swizzled) with warp-private double
// buffering (__syncwarp only), then warps combine partials through SMEM.
__global__ void __launch_bounds__(TPB, 1)
persist_kernel(const float* __restrict__ x, const float* __restrict__ bg,
               const float* __restrict__ bi, float* __restrict__ out,
               int out_size)
{
    const int p = blockIdx.x;
    const int l = p >> 6;
    const int t = threadIdx.x;
    const int wid  = t >> 5;
    const int lane = t & 31;
    const int jg = lane >> 3;    // 0..3 : j-pair group (j = 2jg, 2jg+1)
    const int mg = lane & 7;     // 0..7 : m rows 4mg..4mg+3 and 32+4mg..+3
    const int sL = lane & 3;     // staging k-seg (k = 4sL..4sL+3 within chunk)
    const int mrL = lane >> 2;   // staging m-row part (0..7)

    extern __shared__ float smf[];
    float* ws   = smf;                              // [1024][16] natural weights
    float* bufs = smf + WS_FLOATS;                  // 8 x 1024 floats (2 per warp)
    ull*   px   = (ull*)(smf + WS_FLOATS + 8*ABUF_FLOATS);  // [4][8][64]

    // ---- copy natural weight panel into SMEM once ----
    {
        const float4* gw = ((const float4*)g_Wpanel) + (size_t)p * 4096;
        float4* w4 = (float4*)ws;
        #pragma unroll
        for (int it = 0; it < 32; ++it)
            w4[t + it*TPB] = gw[t + it*TPB];
    }
    __syncthreads();

    const int kb = wid * 256;            // this warp's k base
    float* b0 = bufs + wid*2*ABUF_FLOATS;
    float* b1 = b0 + ABUF_FLOATS;

    const int j = (p & 63)*JPC + (t >> 4);   // epilogue j (t>>4 in 0..7)
    const float bgv = bg[l*HH + j];
    const float biv = bi[l*HH + j];

    unsigned bar_target = 0;

    #pragma unroll 1
    for (int s = 0; s <= SS; ++s){
        const bool active = !((l == 0 && s == SS) || (l == 1 && s == 0));
        if (active){
            int pb = s & 1;
            const float* h0prev  = g_h0[pb ^ 1];
            float*       h0out   = g_h0[pb];
            const float* h1prev2 = g_h1[pb];
            float*       h1out   = g_h1[pb ^ 1];

            // per-warp activation source (k range lies wholly in one matrix)
            const float* src; size_t stride;
            const float* hupd; float* hout;
            if (l == 0){
                if (kb < II){ src = x + (size_t)s*II + kb; stride = (size_t)SS*II; }
                else        { src = h0prev + (kb - II);    stride = HH; }
                hupd = h0prev;  hout = h0out;
            } else {
                if (kb < II){ src = h0prev + kb;           stride = HH; }
                else        { src = h1prev2 + (kb - II);   stride = HH; }
                hupd = h1prev2; hout = h1out;
            }

            // ---- warp-private staging: LDG.128 k-major -> swizzled [k][m] tile ----
            float4 pfv[8];
            auto ldg = [&](int c){
                const float* sc = src + c*KT + 4*sL;
                #pragma unroll
                for (int r = 0; r < 8; ++r){
                    int m = 8*r + mrL;
                    pfv[r] = *(const float4*)(sc + (size_t)m*stride);
                }
            };
            // store element i of pfv[r] (k = 4sL+i, m = 8r+mrL) at
            // row (4sL+i)*64, column ((m>>2) ^ sL)*4 + (m&3)
            auto sts = [&](float* buf){
                float* base = buf + 4*sL*64;
                #pragma unroll
                for (int r = 0; r < 8; ++r){
                    int m = 8*r + mrL;
                    float* d = base + (((m >> 2) ^ sL)*4 + (m & 3));
                    d[0]   = pfv[r].x;
                    d[64]  = pfv[r].y;
                    d[128] = pfv[r].z;
                    d[192] = pfv[r].w;
                }
            };

            ull acc[2][8];
            #pragma unroll
            for (int a2 = 0; a2 < 2; ++a2)
                #pragma unroll
                for (int i = 0; i < 8; ++i) acc[a2][i] = 0ull;

            auto compute = [&](const float* buf, int c){
                const float* wrow = ws + (size_t)(kb + c*KT)*16 + jg*4;
                #pragma unroll
                for (int kk = 0; kk < KT; ++kk){
                    int sk = kk >> 2;
                    const float* arow = buf + kk*64;
                    float4 a0 = *(const float4*)(arow + (mg ^ sk)*4);         // m 4mg..+3
                    float4 a1 = *(const float4*)(arow + ((mg ^ sk) + 8)*4);   // m 32+4mg..+3
                    ulonglong2 w2 = *(const ulonglong2*)(wrow + kk*16);       // (g,c) x 2 j
                    ull pa;
                    pa = packdup(a0.x); acc[0][0]=ffma2(pa,w2.x,acc[0][0]); acc[1][0]=ffma2(pa,w2.y,acc[1][0]);
                    pa = packdup(a0.y); acc[0][1]=ffma2(pa,w2.x,acc[0][1]); acc[1][1]=ffma2(pa,w2.y,acc[1][1]);
                    pa = packdup(a0.z); acc[0][2]=ffma2(pa,w2.x,acc[0][2]); acc[1][2]=ffma2(pa,w2.y,acc[1][2]);
                    pa = packdup(a0.w); acc[0][3]=ffma2(pa,w2.x,acc[0][3]); acc[1][3]=ffma2(pa,w2.y,acc[1][3]);
                    pa = packdup(a1.x); acc[0][4]=ffma2(pa,w2.x,acc[0][4]); acc[1][4]=ffma2(pa,w2.y,acc[1][4]);
                    pa = packdup(a1.y); acc[0][5]=ffma2(pa,w2.x,acc[0][5]); acc[1][5]=ffma2(pa,w2.y,acc[1][5]);
                    pa = packdup(a1.z); acc[0][6]=ffma2(pa,w2.x,acc[0][6]); acc[1][6]=ffma2(pa,w2.y,acc[1][6]);
                    pa = packdup(a1.w); acc[0][7]=ffma2(pa,w2.x,acc[0][7]); acc[1][7]=ffma2(pa,w2.y,acc[1][7]);
                }
            };

            // warp-private pipeline: no CTA syncs in the mainloop
            ldg(0); sts(b0); __syncwarp();
            #pragma unroll 1
            for (int c = 0; c < NCHUNK; ++c){
                if (c + 1 < NCHUNK) ldg(c + 1);
                compute((c & 1) ? b1 : b0, c);
                if (c + 1 < NCHUNK) sts((c & 1) ? b0 : b1);
                __syncwarp();
            }

            // ---- cross-warp k-reduction through SMEM ----
            __syncthreads();
            #pragma unroll
            for (int j2 = 0; j2 < 2; ++j2){
                ull* row = px + (size_t)(wid*8 + 2*jg + j2)*64;
                #pragma unroll
                for (int i = 0; i < 8; ++i){
                    int m = (i < 4) ? (4*mg + i) : (32 + 4*mg + (i - 4));
                    row[m] = acc[j2][i];
                }
            }
            __syncthreads();

            // ---- epilogue: sum 4 warp partials, GRU update ----
            {
                const int jj = t >> 4;          // 0..7
                const int m0 = (t & 15) * 4;    // 4 batch rows
                float gv[4] = {0,0,0,0}, cv[4] = {0,0,0,0};
                #pragma unroll
                for (int w = 0; w < 4; ++w){
                    const ull* row = px + (size_t)(w*8 + jj)*64 + m0;
                    #pragma unroll
                    for (int r = 0; r < 4; ++r){
                        float lo, hi; unpack2(row[r], lo, hi);
                        gv[r] += lo; cv[r] += hi;
                    }
                }
                #pragma unroll
                for (int r = 0; r < 4; ++r){
                    int m = m0 + r;
                    float zin = gv[r] + bgv;
                    float z   = __fdividef(1.f, 1.f + __expf(-zin));
                    float cin = cv[r] + biv;
                    float av  = fabsf(cin);
                    float e   = __expf(-2.f*av);
                    float cd  = copysignf(__fdividef(1.f - e, 1.f + e), cin);
                    float hp  = hupd[(size_t)m*HH + j];
                    float hn  = hp + z*(cd - hp);
                    hout[(size_t)m*HH + j] = hn;
                    if (l == 1)
                        out[(size_t)m*SS*HH + (size_t)(s-1)*HH + j] = hn;
                }
            }
        }

        // ---- grid barrier (monotonic counter; reset by init_kernel each replay) ----
        bar_target += NPANEL;
        __syncthreads();
        if (t == 0){
            __threadfence();
            atomicAdd(&g_arrive, 1u);
            unsigned v;
            do {
                asm volatile("ld.acquire.gpu.global.u32 %0, [%1];"
                             : "=r"(v) : "l"(&g_arrive) : "memory");
            } while (v < bar_target);
        }
        __syncthreads();
    }

    // ---- tail: final hidden states appended after output ----
    // h0[S-1] ended in g_h0[1] (written at phase S-1, pb=1);
    // h1[S-1] ended in g_h1[1] (written at phase S,   pb^1=1).
    long long base = (long long)BB*SS*HH;
    if (base + 2LL*BB*HH <= (long long)out_size){
        for (int i = p*TPB + t; i < BB*HH; i += NPANEL*TPB){
            out[base + i]         = g_h0[1][i];
            out[base + BB*HH + i] = g_h1[1][i];
        }
    }
}

extern "C" void kernel_launch(void* const* d_in, const int* in_sizes, int n_in,
                              void* d_out, int out_size)
{
    const float* x  = (const float*)d_in[0];
    const float* Wg = (const float*)d_in[1];
    const float* bg = (const float*)d_in[2];
    const float* Wi = (const float*)d_in[3];
    const float* bi = (const float*)d_in[4];
    const float* Wh = (const float*)d_in[5];
    float* out = (float*)d_out;

    cudaFuncSetAttribute(persist_kernel, cudaFuncAttributeMaxDynamicSharedMemorySize, SMEM_BYTES);

    prep_kernel<<<(NPANEL*1024*16 + 255)/256, 256>>>(Wg, Wi, Wh);
    init_kernel<<<(BB*HH + 255)/256, 256>>>();
    persist_kernel<<<NPANEL, TPB, SMEM_BYTES>>>(x, bg, bi, out, out_size);
}

// round 11
// speedup vs baseline: 3.6016x; 1.3422x over previous
#include <cuda_runtime.h>
#include <cstdint>
#include <math.h>

// Problem constants
#define BB 64
#define SS 1024
#define II 512
#define HH 512
#define NPANEL 128   // persistent CTAs: 64 panels per layer, 1 CTA/SM
#define JPC 8        // hidden units per CTA
#define TPB 256      // 8 warps; warp w owns k in [128w, 128w+128)
#define NWARP 8
#define KRANGE 128   // k per warp
#define KT 16        // k-chunk staged per warp
#define NCHUNK 8     // 128 / 16

#define WS_FLOATS (1024*16)      // natural weight panel [k][16]: (g0,c0,g1,c1,...)
#define ABUF_FLOATS (KT*64)      // 1024 floats per buffer
#define PX_ULL (NWARP*8*64)      // 4096 ull = 32KB partial-sum exchange
#define SMEM_BYTES ((WS_FLOATS + 2*NWARP*ABUF_FLOATS)*4 + PX_ULL*8)  // 163840 B

typedef unsigned long long ull;

// Scratch (device globals: allocation-free per harness rules)
__device__ float g_Wpanel[NPANEL*1024*16];  // [panel][k][16] cols interleaved (gate j, cand j)
__device__ float g_h0[2][BB*HH];            // ping-pong hidden, layer 0
__device__ float g_h1[2][BB*HH];            // ping-pong hidden, layer 1
__device__ unsigned g_arrive;               // grid-barrier monotonic arrival counter

__device__ __forceinline__ ull ffma2(ull a, ull b, ull c){
    ull d;
    asm("fma.rn.f32x2 %0, %1, %2, %3;" : "=l"(d) : "l"(a), "l"(b), "l"(c));
    return d;
}
__device__ __forceinline__ ull packdup(float a){
    ull r;
    asm("mov.b64 %0, {%1, %1};" : "=l"(r) : "f"(a));
    return r;
}
__device__ __forceinline__ void unpack2(ull v, float& lo, float& hi){
    asm("mov.b64 {%0, %1}, %2;" : "=f"(lo), "=f"(hi) : "l"(v));
}

// Build combined, column-interleaved weight panels (natural, no duplication):
// panel p: layer l = p>>6, hidden units j0..j0+7 with j0 = (p&63)*8.
// g_Wpanel[p][k][2*jj+0] = gate weight Wg[l][k][j]   (Wg rows already [inp;h] ordered)
// g_Wpanel[p][k][2*jj+1] = cand weight (k<512 ? Wi[l][k][j] : Wh[l][k-512][j])
__global__ void prep_kernel(const float* __restrict__ Wg,
                            const float* __restrict__ Wi,
                            const float* __restrict__ Wh){
    int idx = blockIdx.x * blockDim.x + threadIdx.x;
    if (idx >= NPANEL*1024*16) return;
    int cc = idx & 15;
    int k  = (idx >> 4) & 1023;
    int p  = idx >> 14;
    int l  = p >> 6;
    int j  = (p & 63)*JPC + (cc >> 1);
    float v;
    if ((cc & 1) == 0) {
        v = Wg[(size_t)(l*1024 + k)*512 + j];
    } else {
        v = (k < II) ? Wi[(size_t)(l*512 + k)*512 + j]
                     : Wh[(size_t)(l*512 + (k - II))*512 + j];
    }
    g_Wpanel[idx] = v;
}

// Zero hidden state + barrier counter (runs at the start of every replay).
__global__ void init_kernel(){
    int i = blockIdx.x * blockDim.x + threadIdx.x;
    if (i == 0) g_arrive = 0u;
    if (i < BB*HH){
        g_h0[0][i] = 0.f; g_h0[1][i] = 0.f;
        g_h1[0][i] = 0.f; g_h1[1][i] = 0.f;
    }
}

// Persistent kernel: 128 CTAs (one per SM), 256 threads (8 warps, 2 per SMSP),
// phases s=0..SS with a device grid barrier between phases.
//   phase s:  CTAs l==0 compute h0[s]   = gru(x[:,s,:], h0[s-1])   (s < SS)
//             CTAs l==1 compute h1[s-1] = gru(h0[s-1],  h1[s-2])   (s >= 1)
// k-split: warp w owns k in [128w, 128w+128); each warp computes the full
// 8j x 64m x (gate,cand) tile for its k range with 16 f32x2 accumulators,
// stages its own A chunks (16k x 64m, XOR-swizzled) with warp-private double
// buffering (__syncwarp only), then all 8 warps combine partials through SMEM.
// Two warps per SMSP overlap each other's LDS/LDG stalls with zero duplicated
// traffic (disjoint k-ranges; weight reads broadcast).
__global__ void __launch_bounds__(TPB, 1)
persist_kernel(const float* __restrict__ x, const float* __restrict__ bg,
               const float* __restrict__ bi, float* __restrict__ out,
               int out_size)
{
    const int p = blockIdx.x;
    const int l = p >> 6;
    const int t = threadIdx.x;
    const int wid  = t >> 5;
    const int lane = t & 31;
    const int jg = lane >> 3;    // 0..3 : j-pair group (j = 2jg, 2jg+1)
    const int mg = lane & 7;     // 0..7 : m rows 4mg..4mg+3 and 32+4mg..+3
    const int sL = lane & 3;     // staging k-seg (k = 4sL..4sL+3 within chunk)
    const int mrL = lane >> 2;   // staging m-row part (0..7)

    extern __shared__ float smf[];
    float* ws   = smf;                              // [1024][16] natural weights
    float* bufs = smf + WS_FLOATS;                  // 16 x 1024 floats (2 per warp)
    ull*   px   = (ull*)(smf + WS_FLOATS + 2*NWARP*ABUF_FLOATS);  // [8][8][64]

    // ---- copy natural weight panel into SMEM once ----
    {
        const float4* gw = ((const float4*)g_Wpanel) + (size_t)p * 4096;
        float4* w4 = (float4*)ws;
        #pragma unroll
        for (int it = 0; it < 16; ++it)
            w4[t + it*TPB] = gw[t + it*TPB];
    }
    __syncthreads();

    const int kb = wid * KRANGE;         // this warp's k base
    float* b0 = bufs + wid*2*ABUF_FLOATS;
    float* b1 = b0 + ABUF_FLOATS;

    const int jj_e = (t >> 4) & 7;           // epilogue j index 0..7 (threads 0..127)
    const int j = (p & 63)*JPC + jj_e;
    const float bgv = bg[l*HH + j];
    const float biv = bi[l*HH + j];

    unsigned bar_target = 0;

    #pragma unroll 1
    for (int s = 0; s <= SS; ++s){
        const bool active = !((l == 0 && s == SS) || (l == 1 && s == 0));
        if (active){
            int pb = s & 1;
            const float* h0prev  = g_h0[pb ^ 1];
            float*       h0out   = g_h0[pb];
            const float* h1prev2 = g_h1[pb];
            float*       h1out   = g_h1[pb ^ 1];

            // per-warp activation source (k range lies wholly in one matrix)
            const float* src; size_t stride;
            const float* hupd; float* hout;
            if (l == 0){
                if (kb < II){ src = x + (size_t)s*II + kb; stride = (size_t)SS*II; }
                else        { src = h0prev + (kb - II);    stride = HH; }
                hupd = h0prev;  hout = h0out;
            } else {
                if (kb < II){ src = h0prev + kb;           stride = HH; }
                else        { src = h1prev2 + (kb - II);   stride = HH; }
                hupd = h1prev2; hout = h1out;
            }

            // ---- warp-private staging: LDG.128 k-major -> swizzled [k][m] tile ----
            float4 pfv[8];
            auto ldg = [&](int c){
                const float* sc = src + c*KT + 4*sL;
                #pragma unroll
                for (int r = 0; r < 8; ++r){
                    int m = 8*r + mrL;
                    pfv[r] = *(const float4*)(sc + (size_t)m*stride);
                }
            };
            // store element i of pfv[r] (k = 4sL+i, m = 8r+mrL) at
            // row (4sL+i)*64, column ((m>>2) ^ sL)*4 + (m&3)
            auto sts = [&](float* buf){
                float* base = buf + 4*sL*64;
                #pragma unroll
                for (int r = 0; r < 8; ++r){
                    int m = 8*r + mrL;
                    float* d = base + (((m >> 2) ^ sL)*4 + (m & 3));
                    d[0]   = pfv[r].x;
                    d[64]  = pfv[r].y;
                    d[128] = pfv[r].z;
                    d[192] = pfv[r].w;
                }
            };

            ull acc[2][8];
            #pragma unroll
            for (int a2 = 0; a2 < 2; ++a2)
                #pragma unroll
                for (int i = 0; i < 8; ++i) acc[a2][i] = 0ull;

            auto compute = [&](const float* buf, int c){
                const float* wrow = ws + (size_t)(kb + c*KT)*16 + jg*4;
                #pragma unroll
                for (int kk = 0; kk < KT; ++kk){
                    int sk = kk >> 2;
                    const float* arow = buf + kk*64;
                    float4 a0 = *(const float4*)(arow + (mg ^ sk)*4);         // m 4mg..+3
                    float4 a1 = *(const float4*)(arow + ((mg ^ sk) + 8)*4);   // m 32+4mg..+3
                    ulonglong2 w2 = *(const ulonglong2*)(wrow + kk*16);       // (g,c) x 2 j
                    ull pa;
                    pa = packdup(a0.x); acc[0][0]=ffma2(pa,w2.x,acc[0][0]); acc[1][0]=ffma2(pa,w2.y,acc[1][0]);
                    pa = packdup(a0.y); acc[0][1]=ffma2(pa,w2.x,acc[0][1]); acc[1][1]=ffma2(pa,w2.y,acc[1][1]);
                    pa = packdup(a0.z); acc[0][2]=ffma2(pa,w2.x,acc[0][2]); acc[1][2]=ffma2(pa,w2.y,acc[1][2]);
                    pa = packdup(a0.w); acc[0][3]=ffma2(pa,w2.x,acc[0][3]); acc[1][3]=ffma2(pa,w2.y,acc[1][3]);
                    pa = packdup(a1.x); acc[0][4]=ffma2(pa,w2.x,acc[0][4]); acc[1][4]=ffma2(pa,w2.y,acc[1][4]);
                    pa = packdup(a1.y); acc[0][5]=ffma2(pa,w2.x,acc[0][5]); acc[1][5]=ffma2(pa,w2.y,acc[1][5]);
                    pa = packdup(a1.z); acc[0][6]=ffma2(pa,w2.x,acc[0][6]); acc[1][6]=ffma2(pa,w2.y,acc[1][6]);
                    pa = packdup(a1.w); acc[0][7]=ffma2(pa,w2.x,acc[0][7]); acc[1][7]=ffma2(pa,w2.y,acc[1][7]);
                }
            };

            // warp-private pipeline: no CTA syncs in the mainloop
            ldg(0); sts(b0); __syncwarp();
            #pragma unroll 1
            for (int c = 0; c < NCHUNK; ++c){
                if (c + 1 < NCHUNK) ldg(c + 1);
                compute((c & 1) ? b1 : b0, c);
                if (c + 1 < NCHUNK) sts((c & 1) ? b0 : b1);
                __syncwarp();
            }

            // ---- cross-warp k-reduction through SMEM ----
            __syncthreads();
            #pragma unroll
            for (int j2 = 0; j2 < 2; ++j2){
                ull* row = px + (size_t)(wid*8 + 2*jg + j2)*64;
                #pragma unroll
                for (int i = 0; i < 8; ++i){
                    int m = (i < 4) ? (4*mg + i) : (32 + 4*mg + (i - 4));
                    row[m] = acc[j2][i];
                }
            }
            __syncthreads();

            // ---- epilogue: sum 8 warp partials, GRU update (threads 0-127) ----
            if (t < 128){
                const int m0 = (t & 15) * 4;    // 4 batch rows
                float gv[4] = {0,0,0,0}, cv[4] = {0,0,0,0};
                #pragma unroll
                for (int w = 0; w < NWARP; ++w){
                    const ull* row = px + (size_t)(w*8 + jj_e)*64 + m0;
                    #pragma unroll
                    for (int r = 0; r < 4; ++r){
                        float lo, hi; unpack2(row[r], lo, hi);
                        gv[r] += lo; cv[r] += hi;
                    }
                }
                #pragma unroll
                for (int r = 0; r < 4; ++r){
                    int m = m0 + r;
                    float zin = gv[r] + bgv;
                    float z   = __fdividef(1.f, 1.f + __expf(-zin));
                    float cin = cv[r] + biv;
                    float av  = fabsf(cin);
                    float e   = __expf(-2.f*av);
                    float cd  = copysignf(__fdividef(1.f - e, 1.f + e), cin);
                    float hp  = hupd[(size_t)m*HH + j];
                    float hn  = hp + z*(cd - hp);
                    hout[(size_t)m*HH + j] = hn;
                    if (l == 1)
                        out[(size_t)m*SS*HH + (size_t)(s-1)*HH + j] = hn;
                }
            }
        }

        // ---- grid barrier (monotonic counter; reset by init_kernel each replay) ----
        bar_target += NPANEL;
        __syncthreads();
        if (t == 0){
            __threadfence();
            atomicAdd(&g_arrive, 1u);
            unsigned v;
            do {
                asm volatile("ld.acquire.gpu.global.u32 %0, [%1];"
                             : "=r"(v) : "l"(&g_arrive) : "memory");
            } while (v < bar_target);
        }
        __syncthreads();
    }

    // ---- tail: final hidden states appended after output ----
    // h0[S-1] ended in g_h0[1] (written at phase S-1, pb=1);
    // h1[S-1] ended in g_h1[1] (written at phase S,   pb^1=1).
    long long base = (long long)BB*SS*HH;
    if (base + 2LL*BB*HH <= (long long)out_size){
        for (int i = p*TPB + t; i < BB*HH; i += NPANEL*TPB){
            out[base + i]         = g_h0[1][i];
            out[base + BB*HH + i] = g_h1[1][i];
        }
    }
}

extern "C" void kernel_launch(void* const* d_in, const int* in_sizes, int n_in,
                              void* d_out, int out_size)
{
    const float* x  = (const float*)d_in[0];
    const float* Wg = (const float*)d_in[1];
    const float* bg = (const float*)d_in[2];
    const float* Wi = (const float*)d_in[3];
    const float* bi = (const float*)d_in[4];
    const float* Wh = (const float*)d_in[5];
    float* out = (float*)d_out;

    cudaFuncSetAttribute(persist_kernel, cudaFuncAttributeMaxDynamicSharedMemorySize, SMEM_BYTES);

    prep_kernel<<<(NPANEL*1024*16 + 255)/256, 256>>>(Wg, Wi, Wh);
    init_kernel<<<(BB*HH + 255)/256, 256>>>();
    persist_kernel<<<NPANEL, TPB, SMEM_BYTES>>>(x, bg, bi, out, out_size);
}